// round 5
// baseline (speedup 1.0000x reference)
#include <cuda_runtime.h>
#include <cuda_fp16.h>
#include <math.h>
#include <cstdint>

#define CN 8192
#define CD 128
#define CV 3

#define TM 128            // n rows per CTA tile
#define TN 64             // m cols per tile
#define NTILES (CN / TM)  // 64
#define MTILES (CN / TN)  // 128
#define TOTAL_JOBS (NTILES * MTILES)  // 8192

#define RSTRIDE 272       // padded row stride (bytes): conflict-free ldmatrix
#define A_OFF 0
#define A_BYTES (TM * RSTRIDE)                 // 34816
#define B_OFF A_BYTES
#define B_VIEW_BYTES (TN * RSTRIDE)            // 17408
#define B_BUF_BYTES (CV * B_VIEW_BYTES)        // 52224
#define NBUF 3
#define SMEM_TOTAL (B_OFF + NBUF * B_BUF_BYTES)  // 191488

#define NTHREADS 512

#define K2LOG2E 2.8853900817779268  /* 2/ln2 : exp(2*sim) = 2^(sim*K2) */
#define LN2F 0.6931471805599453f

// ---- device scratch ----
__device__ __align__(256) __half g_Hc16[CN * CD];   // pre-scaled by 2/ln2
__device__ __align__(256) __half g_Hv16[CV * CN * CD];
__device__ __align__(256) float g_denom[CV * CN];
__device__ double g_loss;

// ---------------- helpers ----------------
__device__ __forceinline__ uint32_t smem_u32(const void* p) {
    uint32_t a;
    asm("{ .reg .u64 t; cvta.to.shared.u64 t, %1; cvt.u32.u64 %0, t; }" : "=r"(a) : "l"(p));
    return a;
}
__device__ __forceinline__ void cp_async16(uint32_t dst, const void* src) {
    asm volatile("cp.async.cg.shared.global [%0], [%1], 16;" :: "r"(dst), "l"(src));
}
#define CP_COMMIT() asm volatile("cp.async.commit_group;" ::: "memory")
#define CP_WAIT0()  asm volatile("cp.async.wait_group 0;" ::: "memory")
#define CP_WAIT1()  asm volatile("cp.async.wait_group 1;" ::: "memory")

__device__ __forceinline__ void ldm4(uint32_t* r, uint32_t a) {
    asm volatile("ldmatrix.sync.aligned.m8n8.x4.shared.b16 {%0,%1,%2,%3}, [%4];"
                 : "=r"(r[0]), "=r"(r[1]), "=r"(r[2]), "=r"(r[3]) : "r"(a));
}
__device__ __forceinline__ void mma16816h(uint32_t* c, const uint32_t* a, uint32_t b0, uint32_t b1) {
    asm volatile(
        "mma.sync.aligned.m16n8k16.row.col.f16.f16.f16.f16 "
        "{%0,%1}, {%2,%3,%4,%5}, {%6,%7}, {%0,%1};"
        : "+r"(c[0]), "+r"(c[1])
        : "r"(a[0]), "r"(a[1]), "r"(a[2]), "r"(a[3]), "r"(b0), "r"(b1));
}
__device__ __forceinline__ __half2 ex2h2(uint32_t x) {
    uint32_t r;
    asm("ex2.approx.f16x2 %0, %1;" : "=r"(r) : "r"(x));
    return *reinterpret_cast<__half2*>(&r);
}

// ---- kernel 0: zero accumulators ----
__global__ void sg_zero_kernel() {
    int i = blockIdx.x * blockDim.x + threadIdx.x;
    if (i < CV * CN) g_denom[i] = 0.0f;
    if (i == 0) g_loss = 0.0;
}

// ---- kernel 1: L2-normalize rows -> fp16 (Hc pre-scaled by 2/ln2) ----
__global__ void sg_normalize_kernel(const float* __restrict__ Hc,
                                    const float* __restrict__ Hv) {
    int row = blockIdx.x;
    const float* src;
    __half* dst;
    float scale;
    if (row < CN) {
        src = Hc + (size_t)row * CD;
        dst = g_Hc16 + (size_t)row * CD;
        scale = (float)K2LOG2E;
    } else {
        src = Hv + (size_t)(row - CN) * CD;
        dst = g_Hv16 + (size_t)(row - CN) * CD;
        scale = 1.0f;
    }
    int t = threadIdx.x;  // 128 threads
    float x = src[t];
    float ss = x * x;
#pragma unroll
    for (int o = 16; o > 0; o >>= 1) ss += __shfl_xor_sync(0xffffffffu, ss, o);
    __shared__ float ws[4];
    if ((t & 31) == 0) ws[t >> 5] = ss;
    __syncthreads();
    float tot = ws[0] + ws[1] + ws[2] + ws[3];
    float invn = scale / fmaxf(sqrtf(tot), 1e-12f);
    dst[t] = __float2half_rn(x * invn);
}

// ---- smem tile loaders (512 threads) ----
__device__ __forceinline__ void load_A(uint32_t sb, int n0, int t) {
#pragma unroll
    for (int k = 0; k < 4; k++) {
        int q = t + k * NTHREADS;       // 0..2047
        int r = q >> 4;
        int c = q & 15;
        cp_async16(sb + A_OFF + r * RSTRIDE + c * 16,
                   g_Hc16 + (size_t)(n0 + r) * CD + c * 8);
    }
}
__device__ __forceinline__ void load_B(uint32_t sb, int buf, int m0, int t) {
    uint32_t base = sb + B_OFF + buf * B_BUF_BYTES;
#pragma unroll
    for (int k = 0; k < 6; k++) {
        int Q = t + k * NTHREADS;       // 0..3071
        int v = Q >> 10;
        int qq = Q & 1023;
        int r = qq >> 4;
        int c = qq & 15;
        cp_async16(base + v * B_VIEW_BYTES + r * RSTRIDE + c * 16,
                   g_Hv16 + ((size_t)v * CN + (m0 + r)) * CD + c * 8);
    }
}

// ---- kernel 2: HMMA(f16-acc) fused GEMM + exp + weighted denom ----
// 512 threads = 16 warps: grid 8(n) x 2(m); each warp 16n x 32m.
__global__ __launch_bounds__(NTHREADS, 1) void sg_main_kernel(const float* __restrict__ S) {
    extern __shared__ char smem[];
    uint32_t sb = smem_u32(smem);
    const int t = threadIdx.x;
    const int lane = t & 31;
    const int wid = t >> 5;
    const int wn = wid >> 1;     // 0..7 : 16-row group
    const int wm = wid & 1;      // 0..1 : 32-col half
    const int g = lane >> 3;
    const int lr = lane & 7;
    const uint32_t aoff = (uint32_t)(((g & 1) * 8 + lr) * RSTRIDE + (g >> 1) * 16);
    const uint32_t boff = (uint32_t)(((g >> 1) * 8 + lr) * RSTRIDE + (g & 1) * 16);

    const int job0 = (int)(((long long)blockIdx.x * TOTAL_JOBS) / gridDim.x);
    const int job1 = (int)(((long long)(blockIdx.x + 1) * TOTAL_JOBS) / gridDim.x);

    int j = job0;
    while (j < job1) {
        const int nt = j >> 7;
        const int mt0 = j & 127;
        const int jend = min(job1, (nt + 1) << 7);
        const int nTi = jend - j;
        const int n0 = nt * TM;

        __syncthreads();  // previous segment fully done before overwriting smem
        load_A(sb, n0, t);
        load_B(sb, 0, mt0 * TN, t);
        CP_COMMIT();
        if (nTi > 1) { load_B(sb, 1, (mt0 + 1) * TN, t); }
        CP_COMMIT();

        uint32_t af[8][4];              // A frags: 8 ksteps (16 rows per warp)
        float denomAcc[CV][2];          // [view][row-octet]
#pragma unroll
        for (int v = 0; v < CV; v++) { denomAcc[v][0] = 0.0f; denomAcc[v][1] = 0.0f; }

        const int row_base = n0 + wn * 16 + (lane >> 2);
        const int col_base = wm * 32 + 2 * (lane & 3);

        int buf = 0;
        for (int i = 0; i < nTi; i++) {
            if (i + 1 < nTi) CP_WAIT1(); else CP_WAIT0();
            __syncthreads();  // B(i) visible; compute(i-1) done everywhere

            int nbuf = buf + 2; if (nbuf >= 3) nbuf -= 3;
            if (i + 2 < nTi) { load_B(sb, nbuf, (mt0 + i + 2) * TN, t); CP_COMMIT(); }

            if (i == 0) {
                uint32_t abase = sb + A_OFF + (uint32_t)(wn * 16) * RSTRIDE + aoff;
#pragma unroll
                for (int ks = 0; ks < 8; ks++) ldm4(af[ks], abase + ks * 32);
            }

            const int m0 = (mt0 + i) * TN;
            // pre-packed half2 weights: 2 rows (octets) x 4 col-pairs
            __half2 wv[2][4];
#pragma unroll
            for (int oct = 0; oct < 2; oct++) {
                const float* rp = S + (size_t)(row_base + 8 * oct) * CN + (m0 + col_base);
#pragma unroll
                for (int ni = 0; ni < 4; ni++) {
                    float2 x = *reinterpret_cast<const float2*>(rp + ni * 8);
                    wv[oct][ni] = __floats2half2_rn(1.0f - x.x, 1.0f - x.y);
                }
            }

#pragma unroll
            for (int v = 0; v < CV; v++) {
                uint32_t acc[4][2];     // [ni][row-octet] f16x2 col pairs
#pragma unroll
                for (int ni = 0; ni < 4; ni++) { acc[ni][0] = 0u; acc[ni][1] = 0u; }

                uint32_t bbase = sb + B_OFF + buf * B_BUF_BYTES + v * B_VIEW_BYTES +
                                 (uint32_t)(wm * 32) * RSTRIDE + boff;
#pragma unroll
                for (int ks = 0; ks < 8; ks++) {
                    uint32_t bf0[4], bf1[4];
                    ldm4(bf0, bbase + ks * 32);
                    ldm4(bf1, bbase + 16 * RSTRIDE + ks * 32);
                    mma16816h(acc[0], af[ks], bf0[0], bf0[1]);
                    mma16816h(acc[1], af[ks], bf0[2], bf0[3]);
                    mma16816h(acc[2], af[ks], bf1[0], bf1[1]);
                    mma16816h(acc[3], af[ks], bf1[2], bf1[3]);
                }
                // epilogue: acc holds log2(exp(2*sim)); denom += w * 2^acc (half2)
                __half2 h0 = __floats2half2_rn(0.0f, 0.0f);
                __half2 h1 = h0;
#pragma unroll
                for (int ni = 0; ni < 4; ni++) {
                    h0 = __hfma2(wv[0][ni], ex2h2(acc[ni][0]), h0);
                    h1 = __hfma2(wv[1][ni], ex2h2(acc[ni][1]), h1);
                }
                float2 f0 = __half22float2(h0);
                float2 f1 = __half22float2(h1);
                denomAcc[v][0] += f0.x + f0.y;
                denomAcc[v][1] += f1.x + f1.y;
            }
            buf++; if (buf >= 3) buf -= 3;
        }

        // flush denominators (reduce over lane&3 = distinct col groups)
#pragma unroll
        for (int v = 0; v < CV; v++)
#pragma unroll
            for (int oct = 0; oct < 2; oct++) {
                float val = denomAcc[v][oct];
                val += __shfl_xor_sync(0xffffffffu, val, 1);
                val += __shfl_xor_sync(0xffffffffu, val, 2);
                if ((lane & 3) == 0)
                    atomicAdd(&g_denom[v * CN + row_base + 8 * oct], val);
            }
        j = jend;
    }
}

// ---- kernel 3: positives + loss reduction ----
// g_Hc16 pre-scaled by 2/ln2 -> positive = (scaled dot) * ln2
__global__ void sg_finalize_kernel() {
    int gwarp = (blockIdx.x * blockDim.x + threadIdx.x) >> 5;
    int lane = threadIdx.x & 31;
    int v = gwarp / CN;
    int n = gwarp % CN;
    const __half* a = g_Hc16 + (size_t)n * CD;
    const __half* b = g_Hv16 + (size_t)v * CN * CD + (size_t)n * CD;
    float s = 0.0f;
#pragma unroll
    for (int k = 0; k < CD / 32; k++)
        s += __half2float(a[lane + 32 * k]) * __half2float(b[lane + 32 * k]);
#pragma unroll
    for (int o = 16; o > 0; o >>= 1) s += __shfl_xor_sync(0xffffffffu, s, o);

    __shared__ double part[8];
    if (lane == 0) {
        float den = fmaxf(g_denom[gwarp], 1e-9f);
        part[threadIdx.x >> 5] = (double)(logf(den) - s * LN2F);
    }
    __syncthreads();
    if (threadIdx.x == 0) {
        double bs = 0.0;
#pragma unroll
        for (int w = 0; w < 8; w++) bs += part[w];
        atomicAdd(&g_loss, bs);
    }
}

// ---- kernel 4: write scalar output ----
__global__ void sg_writeout_kernel(float* out) {
    out[0] = (float)(g_loss / (double)((long long)CN * CV));
}

extern "C" void kernel_launch(void* const* d_in, const int* in_sizes, int n_in,
                              void* d_out, int out_size) {
    const float* Hc = (const float*)d_in[0];
    const float* S = (const float*)d_in[1];
    const float* Hv = (const float*)d_in[2];
    float* out = (float*)d_out;

    int nsm = 148;
    cudaDeviceGetAttribute(&nsm, cudaDevAttrMultiProcessorCount, 0);

    cudaFuncSetAttribute(sg_main_kernel, cudaFuncAttributeMaxDynamicSharedMemorySize,
                         SMEM_TOTAL);

    sg_zero_kernel<<<(CV * CN + 255) / 256, 256>>>();
    sg_normalize_kernel<<<(CV + 1) * CN, 128>>>(Hc, Hv);
    sg_main_kernel<<<nsm, NTHREADS, SMEM_TOTAL>>>(S);
    sg_finalize_kernel<<<(CV * CN) / 8, 256>>>();
    sg_writeout_kernel<<<1, 1>>>(out);
}